// round 2
// baseline (speedup 1.0000x reference)
#include <cuda_runtime.h>

// Problem constants
#define B_ROWS 16
#define NCOL 2048
#define M 4096          // flat rows
#define D 8
#define NC 65536
#define ROWS_PER_M 256  // flat rows per batch row

// Argmin tunables
#define R_PER_THREAD 2
#define NWARPS 8
#define ROWS_PER_BLOCK (NWARPS * R_PER_THREAD)   // 16
#define NSEG 4
#define SEG_CODES (NC / NSEG)                    // 16384
#define TILE 512                                 // codes per shared tile
#define TILE2 (TILE / 2)                         // code-pairs per tile

typedef unsigned long long ull;

// Scratch
__device__ float g_scale[B_ROWS];
__device__ float g_cnorm[NC];
__device__ ull   g_key[M];          // (monotone dist bits << 32) | idx
__device__ float g_sums[NC * D];
__device__ float g_counts[NC];

__device__ __forceinline__ ull pack2(float lo, float hi) {
    ull r;
    asm("mov.b64 %0, {%1, %2};" : "=l"(r) : "f"(lo), "f"(hi));
    return r;
}
__device__ __forceinline__ void unpack2(ull v, float& lo, float& hi) {
    asm("mov.b64 {%0, %1}, %2;" : "=f"(lo), "=f"(hi) : "l"(v));
}
__device__ __forceinline__ void fma2(ull& d, ull a, ull b) {
    asm("fma.rn.f32x2 %0, %1, %2, %3;" : "=l"(d) : "l"(a), "l"(b), "l"(d));
}

// ---------------------------------------------------------------------------
__global__ void k_scale(const float* __restrict__ x) {
    __shared__ float sh[256];
    int b = blockIdx.x;
    const float* row = x + b * NCOL;
    float s = 0.f;
    for (int i = threadIdx.x; i < NCOL; i += blockDim.x) s += fabsf(row[i]);
    sh[threadIdx.x] = s;
    __syncthreads();
    for (int off = 128; off > 0; off >>= 1) {
        if (threadIdx.x < off) sh[threadIdx.x] += sh[threadIdx.x + off];
        __syncthreads();
    }
    if (threadIdx.x == 0) g_scale[b] = sh[0] * (1.0f / NCOL);
}

// ---------------------------------------------------------------------------
__global__ void k_cnorm(const float* __restrict__ cb) {
    int c = blockIdx.x * blockDim.x + threadIdx.x;
    if (c < NC) {
        const float4* p = (const float4*)(cb + c * D);
        float4 a = p[0], b4 = p[1];
        g_cnorm[c] = a.x * a.x + a.y * a.y + a.z * a.z + a.w * a.w +
                     b4.x * b4.x + b4.y * b4.y + b4.z * b4.z + b4.w * b4.w;
    }
}

// ---------------------------------------------------------------------------
__global__ void k_init() {
    int t = blockIdx.x * blockDim.x + threadIdx.x;
    if (t < NC * D) g_sums[t] = 0.f;
    if (t < NC) g_counts[t] = 0.f;
    if (t < M) g_key[t] = 0xFFFFFFFFFFFFFFFFull;
}

// ---------------------------------------------------------------------------
// Argmin: grid = (M/ROWS_PER_BLOCK, NSEG), 256 threads.
// Shared tile: interleaved code-pairs. sh4[j2][c2] holds
//   (cb[2c2][2j2], cb[2c2+1][2j2], cb[2c2][2j2+1], cb[2c2+1][2j2+1])
// so .xy / .zw are FFMA2 operands for one dim across two adjacent codes.
// Query registers hold duplicated (-2*f_j, -2*f_j) pairs.
// d = |c|^2 - 2 f.c accumulated with fma.rn.f32x2 (2 codes per instr).
// ---------------------------------------------------------------------------
__global__ void __launch_bounds__(256) k_argmin(const float* __restrict__ x,
                                                const float* __restrict__ cb) {
    __shared__ float4 sh4[4][TILE2];   // 16 KB
    __shared__ float2 shcn[TILE2];     // 2 KB

    int row0 = blockIdx.x * ROWS_PER_BLOCK;
    int segBase = blockIdx.y * SEG_CODES;
    int ct = threadIdx.x & 31;
    int w = threadIdx.x >> 5;
    int myrow0 = row0 + w * R_PER_THREAD;

    // Load my rows: pack duplicated (-2*x/scale) pairs
    ull f2[R_PER_THREAD][D];
#pragma unroll
    for (int r = 0; r < R_PER_THREAD; r++) {
        int m = myrow0 + r;
        float c0 = -2.0f / g_scale[m / ROWS_PER_M];
        const float* xr = x + m * D;
#pragma unroll
        for (int j = 0; j < D; j++) {
            float v = xr[j] * c0;
            f2[r][j] = pack2(v, v);
        }
    }

    float dmin[R_PER_THREAD];
    int imin[R_PER_THREAD];
#pragma unroll
    for (int r = 0; r < R_PER_THREAD; r++) { dmin[r] = 3.4e38f; imin[r] = 0; }

    const float4* cbv = (const float4*)cb;   // [NC][2] float4s per code

    for (int t0 = 0; t0 < SEG_CODES; t0 += TILE) {
        __syncthreads();
        // Stage: tasks = TILE2 code-pairs x 2 halves = 512, 256 threads -> 2 each
#pragma unroll
        for (int q = threadIdx.x; q < TILE2 * 2; q += 256) {
            int c2 = q >> 1;
            int h = q & 1;                    // dims 4h..4h+3
            int code0 = segBase + t0 + 2 * c2;
            float4 a = cbv[code0 * 2 + h];
            float4 b = cbv[code0 * 2 + 2 + h];  // code0+1
            sh4[2 * h + 0][c2] = make_float4(a.x, b.x, a.y, b.y);
            sh4[2 * h + 1][c2] = make_float4(a.z, b.z, a.w, b.w);
        }
        {
            int t = threadIdx.x;  // 256 threads == TILE2
            shcn[t] = ((const float2*)g_cnorm)[(segBase + t0) / 2 + t];
        }
        __syncthreads();

        int kBase = segBase + t0;
#pragma unroll
        for (int i = 0; i < TILE2 / 32; i++) {
            int c2 = ct + 32 * i;
            const ulonglong2* p0 = (const ulonglong2*)&sh4[0][c2];
            const ulonglong2* p1 = (const ulonglong2*)&sh4[1][c2];
            const ulonglong2* p2 = (const ulonglong2*)&sh4[2][c2];
            const ulonglong2* p3 = (const ulonglong2*)&sh4[3][c2];
            ulonglong2 q0 = *p0, q1 = *p1, q2 = *p2, q3 = *p3;
            ull cn2 = *(const ull*)&shcn[c2];
            int gidx = kBase + 2 * c2;
#pragma unroll
            for (int r = 0; r < R_PER_THREAD; r++) {
                ull d = cn2;
                fma2(d, f2[r][0], q0.x);
                fma2(d, f2[r][1], q0.y);
                fma2(d, f2[r][2], q1.x);
                fma2(d, f2[r][3], q1.y);
                fma2(d, f2[r][4], q2.x);
                fma2(d, f2[r][5], q2.y);
                fma2(d, f2[r][6], q3.x);
                fma2(d, f2[r][7], q3.y);
                float de, dodd;
                unpack2(d, de, dodd);
                if (de < dmin[r]) { dmin[r] = de; imin[r] = gidx; }
                if (dodd < dmin[r]) { dmin[r] = dodd; imin[r] = gidx + 1; }
            }
        }
    }

    // Warp reduction across 32 code lanes (warp shares the same rows)
#pragma unroll
    for (int r = 0; r < R_PER_THREAD; r++) {
        float d = dmin[r];
        int i = imin[r];
        for (int off = 16; off > 0; off >>= 1) {
            float d2 = __shfl_down_sync(0xffffffffu, d, off);
            int i2 = __shfl_down_sync(0xffffffffu, i, off);
            if (d2 < d || (d2 == d && i2 < i)) { d = d2; i = i2; }
        }
        if (ct == 0) {
            unsigned int ud = __float_as_uint(d);
            ud = (ud & 0x80000000u) ? ~ud : (ud | 0x80000000u);
            ull key = ((ull)ud << 32) | (unsigned int)i;
            atomicMin(&g_key[myrow0 + r], key);
        }
    }
}

// ---------------------------------------------------------------------------
__global__ void k_scatter(const float* __restrict__ x) {
    int m = blockIdx.x * blockDim.x + threadIdx.x;
    if (m >= M) return;
    int idx = (int)(g_key[m] & 0xFFFFFFFFu);
    float inv = 1.0f / g_scale[m / ROWS_PER_M];
    atomicAdd(&g_counts[idx], 1.f);
    const float* xr = x + m * D;
#pragma unroll
    for (int j = 0; j < D; j++) atomicAdd(&g_sums[idx * D + j], xr[j] * inv);
}

// ---------------------------------------------------------------------------
__global__ void k_gather(float* __restrict__ out) {
    int t = blockIdx.x * blockDim.x + threadIdx.x;
    if (t >= M * D) return;
    int m = t >> 3;
    int j = t & 7;
    int idx = (int)(g_key[m] & 0xFFFFFFFFu);
    float cnt = g_counts[idx];
    cnt = cnt < 1.f ? 1.f : cnt;
    out[t] = g_scale[m / ROWS_PER_M] * (g_sums[idx * D + j] / cnt);
}

// ---------------------------------------------------------------------------
extern "C" void kernel_launch(void* const* d_in, const int* in_sizes, int n_in,
                              void* d_out, int out_size) {
    const float* x = (const float*)d_in[0];
    const float* cb = (const float*)d_in[1];
    if (n_in >= 2 && in_sizes[0] > in_sizes[1]) {
        x = (const float*)d_in[1];
        cb = (const float*)d_in[0];
    }
    float* out = (float*)d_out;

    k_scale<<<B_ROWS, 256>>>(x);
    k_cnorm<<<NC / 256, 256>>>(cb);
    k_init<<<(NC * D + 255) / 256, 256>>>();
    dim3 grid(M / ROWS_PER_BLOCK, NSEG);
    k_argmin<<<grid, 256>>>(x, cb);
    k_scatter<<<(M + 255) / 256, 256>>>(x);
    k_gather<<<(M * D + 255) / 256, 256>>>(out);
}

// round 3
// speedup vs baseline: 1.5237x; 1.5237x over previous
#include <cuda_runtime.h>

// Problem constants
#define B_ROWS 16
#define NCOL 2048
#define M 4096          // flat rows
#define D 8
#define NC 65536
#define ROWS_PER_M 256  // flat rows per batch row

// Argmin tunables
#define R_PER_THREAD 4
#define NWARPS 8
#define ROWS_PER_BLOCK (NWARPS * R_PER_THREAD)   // 32
#define NSEG 8
#define SEG_CODES (NC / NSEG)                    // 8192
#define TILE 512                                 // codes per shared tile
#define TILE2 (TILE / 2)                         // code-pairs per tile

typedef unsigned long long ull;

// Scratch
__device__ float g_scale[B_ROWS];
__device__ float g_cnorm[NC];
__device__ ull   g_key[M];          // (monotone dist bits << 32) | idx
__device__ float g_sums[NC * D];
__device__ float g_counts[NC];

__device__ __forceinline__ ull pack2(float lo, float hi) {
    ull r;
    asm("mov.b64 %0, {%1, %2};" : "=l"(r) : "f"(lo), "f"(hi));
    return r;
}
__device__ __forceinline__ void unpack2(ull v, float& lo, float& hi) {
    asm("mov.b64 {%0, %1}, %2;" : "=f"(lo), "=f"(hi) : "l"(v));
}
__device__ __forceinline__ void fma2(ull& d, ull a, ull b) {
    asm("fma.rn.f32x2 %0, %1, %2, %3;" : "=l"(d) : "l"(a), "l"(b), "l"(d));
}

// ---------------------------------------------------------------------------
__global__ void k_scale(const float* __restrict__ x) {
    __shared__ float sh[256];
    int b = blockIdx.x;
    const float* row = x + b * NCOL;
    float s = 0.f;
    for (int i = threadIdx.x; i < NCOL; i += blockDim.x) s += fabsf(row[i]);
    sh[threadIdx.x] = s;
    __syncthreads();
    for (int off = 128; off > 0; off >>= 1) {
        if (threadIdx.x < off) sh[threadIdx.x] += sh[threadIdx.x + off];
        __syncthreads();
    }
    if (threadIdx.x == 0) g_scale[b] = sh[0] * (1.0f / NCOL);
}

// ---------------------------------------------------------------------------
__global__ void k_cnorm(const float* __restrict__ cb) {
    int c = blockIdx.x * blockDim.x + threadIdx.x;
    if (c < NC) {
        const float4* p = (const float4*)(cb + c * D);
        float4 a = p[0], b4 = p[1];
        g_cnorm[c] = a.x * a.x + a.y * a.y + a.z * a.z + a.w * a.w +
                     b4.x * b4.x + b4.y * b4.y + b4.z * b4.z + b4.w * b4.w;
    }
}

// ---------------------------------------------------------------------------
__global__ void k_init() {
    int t = blockIdx.x * blockDim.x + threadIdx.x;
    if (t < NC * D) g_sums[t] = 0.f;
    if (t < NC) g_counts[t] = 0.f;
    if (t < M) g_key[t] = 0xFFFFFFFFFFFFFFFFull;
}

// ---------------------------------------------------------------------------
// Argmin: grid = (M/ROWS_PER_BLOCK, NSEG), 256 threads, R=4 rows/thread.
// Shared tile: interleaved code-pairs so LDS.128 yields two FFMA2 operands:
//   sh4[j2][c2] = (cb[2c2][2j2], cb[2c2+1][2j2], cb[2c2][2j2+1], cb[2c2+1][2j2+1])
// Query registers hold duplicated (-2*f_j, -2*f_j) pairs; d = |c|^2 - 2 f.c
// accumulated via fma.rn.f32x2 (2 codes per instruction, 4 rows reuse per load).
// ---------------------------------------------------------------------------
__global__ void __launch_bounds__(256, 2) k_argmin(const float* __restrict__ x,
                                                   const float* __restrict__ cb) {
    __shared__ float4 sh4[4][TILE2];   // 16 KB
    __shared__ float2 shcn[TILE2];     // 2 KB

    int row0 = blockIdx.x * ROWS_PER_BLOCK;
    int segBase = blockIdx.y * SEG_CODES;
    int ct = threadIdx.x & 31;
    int w = threadIdx.x >> 5;
    int myrow0 = row0 + w * R_PER_THREAD;

    // Load my rows: duplicated (-2*x/scale) pairs
    ull f2[R_PER_THREAD][D];
#pragma unroll
    for (int r = 0; r < R_PER_THREAD; r++) {
        int m = myrow0 + r;
        float c0 = -2.0f / g_scale[m / ROWS_PER_M];
        const float4* xr = (const float4*)(x + m * D);
        float4 a = xr[0], b = xr[1];
        f2[r][0] = pack2(a.x * c0, a.x * c0);
        f2[r][1] = pack2(a.y * c0, a.y * c0);
        f2[r][2] = pack2(a.z * c0, a.z * c0);
        f2[r][3] = pack2(a.w * c0, a.w * c0);
        f2[r][4] = pack2(b.x * c0, b.x * c0);
        f2[r][5] = pack2(b.y * c0, b.y * c0);
        f2[r][6] = pack2(b.z * c0, b.z * c0);
        f2[r][7] = pack2(b.w * c0, b.w * c0);
    }

    float dmin[R_PER_THREAD];
    int imin[R_PER_THREAD];
#pragma unroll
    for (int r = 0; r < R_PER_THREAD; r++) { dmin[r] = 3.4e38f; imin[r] = 0; }

    const float4* cbv = (const float4*)cb;   // 2 float4s per code

    for (int t0 = 0; t0 < SEG_CODES; t0 += TILE) {
        __syncthreads();
        // Stage: TILE2 pairs x 2 halves = 512 tasks, 2 per thread
#pragma unroll
        for (int q = threadIdx.x; q < TILE2 * 2; q += 256) {
            int c2 = q >> 1;
            int h = q & 1;                    // dims 4h..4h+3
            int code0 = segBase + t0 + 2 * c2;
            float4 a = cbv[code0 * 2 + h];
            float4 b = cbv[code0 * 2 + 2 + h];
            sh4[2 * h + 0][c2] = make_float4(a.x, b.x, a.y, b.y);
            sh4[2 * h + 1][c2] = make_float4(a.z, b.z, a.w, b.w);
        }
        shcn[threadIdx.x] = ((const float2*)g_cnorm)[(segBase + t0) / 2 + threadIdx.x];
        __syncthreads();

        int kBase = segBase + t0;
#pragma unroll 4
        for (int i = 0; i < TILE2 / 32; i++) {
            int c2 = ct + 32 * i;
            ulonglong2 q0 = *(const ulonglong2*)&sh4[0][c2];
            ulonglong2 q1 = *(const ulonglong2*)&sh4[1][c2];
            ulonglong2 q2 = *(const ulonglong2*)&sh4[2][c2];
            ulonglong2 q3 = *(const ulonglong2*)&sh4[3][c2];
            ull cn2 = *(const ull*)&shcn[c2];
            int gidx = kBase + 2 * c2;
#pragma unroll
            for (int r = 0; r < R_PER_THREAD; r++) {
                ull d = cn2;
                fma2(d, f2[r][0], q0.x);
                fma2(d, f2[r][1], q0.y);
                fma2(d, f2[r][2], q1.x);
                fma2(d, f2[r][3], q1.y);
                fma2(d, f2[r][4], q2.x);
                fma2(d, f2[r][5], q2.y);
                fma2(d, f2[r][6], q3.x);
                fma2(d, f2[r][7], q3.y);
                float de, dodd;
                unpack2(d, de, dodd);
                if (de < dmin[r]) { dmin[r] = de; imin[r] = gidx; }
                if (dodd < dmin[r]) { dmin[r] = dodd; imin[r] = gidx + 1; }
            }
        }
    }

    // Warp reduction across 32 code lanes (warp shares the same rows)
#pragma unroll
    for (int r = 0; r < R_PER_THREAD; r++) {
        float d = dmin[r];
        int i = imin[r];
        for (int off = 16; off > 0; off >>= 1) {
            float d2 = __shfl_down_sync(0xffffffffu, d, off);
            int i2 = __shfl_down_sync(0xffffffffu, i, off);
            if (d2 < d || (d2 == d && i2 < i)) { d = d2; i = i2; }
        }
        if (ct == 0) {
            unsigned int ud = __float_as_uint(d);
            ud = (ud & 0x80000000u) ? ~ud : (ud | 0x80000000u);
            ull key = ((ull)ud << 32) | (unsigned int)i;
            atomicMin(&g_key[myrow0 + r], key);
        }
    }
}

// ---------------------------------------------------------------------------
__global__ void k_scatter(const float* __restrict__ x) {
    int m = blockIdx.x * blockDim.x + threadIdx.x;
    if (m >= M) return;
    int idx = (int)(g_key[m] & 0xFFFFFFFFu);
    float inv = 1.0f / g_scale[m / ROWS_PER_M];
    atomicAdd(&g_counts[idx], 1.f);
    const float* xr = x + m * D;
#pragma unroll
    for (int j = 0; j < D; j++) atomicAdd(&g_sums[idx * D + j], xr[j] * inv);
}

// ---------------------------------------------------------------------------
__global__ void k_gather(float* __restrict__ out) {
    int t = blockIdx.x * blockDim.x + threadIdx.x;
    if (t >= M * D) return;
    int m = t >> 3;
    int j = t & 7;
    int idx = (int)(g_key[m] & 0xFFFFFFFFu);
    float cnt = g_counts[idx];
    cnt = cnt < 1.f ? 1.f : cnt;
    out[t] = g_scale[m / ROWS_PER_M] * (g_sums[idx * D + j] / cnt);
}

// ---------------------------------------------------------------------------
extern "C" void kernel_launch(void* const* d_in, const int* in_sizes, int n_in,
                              void* d_out, int out_size) {
    const float* x = (const float*)d_in[0];
    const float* cb = (const float*)d_in[1];
    if (n_in >= 2 && in_sizes[0] > in_sizes[1]) {
        x = (const float*)d_in[1];
        cb = (const float*)d_in[0];
    }
    float* out = (float*)d_out;

    k_scale<<<B_ROWS, 256>>>(x);
    k_cnorm<<<NC / 256, 256>>>(cb);
    k_init<<<(NC * D + 255) / 256, 256>>>();
    dim3 grid(M / ROWS_PER_BLOCK, NSEG);
    k_argmin<<<grid, 256>>>(x, cb);
    k_scatter<<<(M + 255) / 256, 256>>>(x);
    k_gather<<<(M * D + 255) / 256, 256>>>(out);
}